// round 16
// baseline (speedup 1.0000x reference)
#include <cuda_runtime.h>
#include <cuda_fp16.h>
#include <cstdint>
#include <cstring>
#include <math.h>

#define Nn 50000
#define Ee 200000
#define Hd 128
#define Cc 4
#define Gg 64
#define EDd 16
#define NROWS (Cc*Nn)   // 200000
#define NBLK_SCAN ((Nn + 1023)/1024)   // 49
#define MLP_GRID 152

// ---------------- scratch (device globals; no allocation allowed) ----------------
__device__ __align__(128) __half g_eeh[Ee*Hd];
__device__ __align__(128) __half g_xh[NROWS*Hd];
__device__ __align__(128) __half g_bufA[NROWS*Hd];
__device__ __align__(128) __half g_bufB[NROWS*Hd];
__device__ int g_deg[Nn];
__device__ int g_offs[Nn+1];
__device__ int g_cnt[Nn];
__device__ int g_csr[Ee];
__device__ int g_gstart[Gg+1];
__device__ int g_bsum[NBLK_SCAN];
__device__ int g_boff[NBLK_SCAN+1];
// fp16 weights: 6 matrices x 16384, row-major [k][n]
__device__ __align__(128) __half g_wsp[6*16384];

__device__ __forceinline__ float gelu_f(float v){
    return 0.5f*v*(1.0f+erff(v*0.7071067811865475f));
}

__device__ __forceinline__ uint32_t smem_u32(const void* p){
    uint32_t a;
    asm("{ .reg .u64 t; cvta.to.shared.u64 t, %1; cvt.u32.u64 %0, t; }" : "=r"(a) : "l"(p));
    return a;
}
__device__ __forceinline__ void ldsm_x4(uint32_t& r0, uint32_t& r1, uint32_t& r2, uint32_t& r3, uint32_t addr){
    asm volatile("ldmatrix.sync.aligned.m8n8.x4.shared.b16 {%0,%1,%2,%3}, [%4];"
        : "=r"(r0), "=r"(r1), "=r"(r2), "=r"(r3) : "r"(addr));
}
__device__ __forceinline__ void ldsm_x4t(uint32_t* r, uint32_t addr){
    asm volatile("ldmatrix.sync.aligned.m8n8.x4.trans.shared.b16 {%0,%1,%2,%3}, [%4];"
        : "=r"(r[0]), "=r"(r[1]), "=r"(r[2]), "=r"(r[3]) : "r"(addr));
}
__device__ __forceinline__ void mma_fp16(float* c, const uint32_t* a, uint32_t b0, uint32_t b1){
    asm volatile("mma.sync.aligned.m16n8k16.row.col.f32.f16.f16.f32 "
        "{%0,%1,%2,%3},{%4,%5,%6,%7},{%8,%9},{%0,%1,%2,%3};"
        : "+f"(c[0]), "+f"(c[1]), "+f"(c[2]), "+f"(c[3])
        : "r"(a[0]), "r"(a[1]), "r"(a[2]), "r"(a[3]), "r"(b0), "r"(b1));
}
__device__ __forceinline__ uint32_t pack_h2(float a, float b){
    __half2 t = __floats2half2_rn(a, b);
    uint32_t u; memcpy(&u, &t, 4); return u;
}
#define BARW(id) asm volatile("bar.sync %0, 128;" :: "r"(id) : "memory")

// ---------------- weight prep: fp32 -> fp16 (all 6 mats) ----------------
__global__ void k_prepw_all(const float* __restrict__ W1, const float* __restrict__ W2,
                            const float* __restrict__ Wm1, const float* __restrict__ Wm2,
                            __half* __restrict__ outw){
    int mat = blockIdx.y;
    const float* src;
    switch (mat){
        case 0: src = W1;          break;
        case 1: src = W2;          break;
        case 2: src = W1 + 16384;  break;
        case 3: src = W2 + 16384;  break;
        case 4: src = Wm1;         break;
        default: src = Wm2;        break;
    }
    int idx = blockIdx.x*256 + threadIdx.x;
    if (idx >= 16384) return;
    outw[mat*16384 + idx] = __float2half_rn(src[idx]);
}

// ---------------- x fp32 -> fp16 ----------------
__global__ void k_x2h(const float* __restrict__ x, __half* __restrict__ xh){
    int i = blockIdx.x*256 + threadIdx.x;
    if (i < NROWS*Hd/4){
        float4 v = ((const float4*)x)[i];
        uint2 o; o.x = pack_h2(v.x, v.y); o.y = pack_h2(v.z, v.w);
        ((uint2*)xh)[i] = o;
    }
}

// ---------------- bond encoder via mma (single fp16 W term) ----------------
#define LDB_A 24
__global__ void __launch_bounds__(512, 2)
k_bond_mma(const float* __restrict__ ea, const float* __restrict__ Wbe,
           const float* __restrict__ bbe){
    __shared__ __half sA[256*LDB_A];
    __shared__ __half sWh[16*136];
    const int tid = threadIdx.x;
    const int base = blockIdx.x*256;

    #pragma unroll
    for (int i = tid; i < 2048; i += 512){
        int k = i >> 7, n = i & 127;
        sWh[k*136 + n] = __float2half_rn(Wbe[i]);
    }
    #pragma unroll
    for (int i = tid; i < 1024; i += 512){
        int row = i >> 2, c4 = (i & 3)*4;
        float4 v = make_float4(0.f,0.f,0.f,0.f);
        if (base + row < Ee) v = *(const float4*)&ea[(size_t)(base+row)*EDd + c4];
        uint2 o; o.x = pack_h2(v.x, v.y); o.y = pack_h2(v.z, v.w);
        *(uint2*)&sA[row*LDB_A + c4] = o;
    }
    __syncthreads();

    const uint32_t sbA = smem_u32(sA), sbWh = smem_u32(sWh);
    const int w = tid >> 5, lane = tid & 31;
    const int wm = w & 7, wn = w >> 3;
    const int m0 = wm*32;
    const int grp = lane >> 2, quad = lane & 3;

    uint32_t a0[4], a1[4];
    {
        uint32_t aaddr = sbA + 2u*((uint32_t)((m0 + (lane&15))*LDB_A + (lane>>4)*8));
        ldsm_x4(a0[0], a0[1], a0[2], a0[3], aaddr);
        ldsm_x4(a1[0], a1[1], a1[2], a1[3], aaddr + 16*LDB_A*2);
    }
    float acc[2][8][4];
    #pragma unroll
    for (int mt = 0; mt < 2; mt++)
        #pragma unroll
        for (int nt = 0; nt < 8; nt++){ acc[mt][nt][0]=0.f; acc[mt][nt][1]=0.f; acc[mt][nt][2]=0.f; acc[mt][nt][3]=0.f; }

    {
        uint32_t bh_base = sbWh + 2u*((uint32_t)((lane&15)*136 + wn*64 + (lane>>4)*8));
        #pragma unroll
        for (int ntp = 0; ntp < 4; ntp++){
            uint32_t bh[4];
            ldsm_x4t(bh, bh_base + ntp*32);
            mma_fp16(acc[0][2*ntp],   a0, bh[0], bh[1]);
            mma_fp16(acc[1][2*ntp],   a1, bh[0], bh[1]);
            mma_fp16(acc[0][2*ntp+1], a0, bh[2], bh[3]);
            mma_fp16(acc[1][2*ntp+1], a1, bh[2], bh[3]);
        }
    }
    #pragma unroll
    for (int mt = 0; mt < 2; mt++){
        int r0 = m0 + mt*16 + grp, r1 = r0 + 8;
        bool v0 = (base + r0) < Ee, v1 = (base + r1) < Ee;
        #pragma unroll
        for (int nt = 0; nt < 8; nt++){
            int n = wn*64 + nt*8 + quad*2;
            float b0 = bbe[n], b1 = bbe[n+1];
            if (v0) *(uint32_t*)&g_eeh[(size_t)(base+r0)*Hd + n] = pack_h2(acc[mt][nt][0]+b0, acc[mt][nt][1]+b1);
            if (v1) *(uint32_t*)&g_eeh[(size_t)(base+r1)*Hd + n] = pack_h2(acc[mt][nt][2]+b0, acc[mt][nt][3]+b1);
        }
    }
}

// ---------------- persistent mma MLP (single fp16 W term) ----------------
#define LDA 136
#define SM_A0  0
#define SM_A1  (128*LDA)
#define SM_WAH (256*LDA)
#define SM_WBH (256*LDA + 128*LDA)
#define SMEM_MMA ((256*LDA + 2*128*LDA)*2)   // 139264 bytes

__device__ __forceinline__ void cp_async16(uint32_t dst, const void* src, int nbytes){
    asm volatile("cp.async.ca.shared.global [%0], [%1], 16, %2;"
        :: "r"(dst), "l"(src), "r"(nbytes));
}
#define CP_COMMIT() asm volatile("cp.async.commit_group;" ::: "memory")
#define CP_WAIT0()  asm volatile("cp.async.wait_group 0;" ::: "memory")

__device__ __forceinline__ void load_A_async(uint32_t sbuf, const __half* __restrict__ in,
                                             int base, int rows, int tid){
    #pragma unroll
    for (int i = tid; i < 2048; i += 512){
        int row = i >> 4, c8 = (i & 15)*8;
        uint32_t dst = sbuf + 2u*((uint32_t)(row*LDA + c8));
        int r = base + row;
        int nb = (r < rows) ? 16 : 0;
        if (r >= rows) r = rows - 1;              // clamp: address always in-bounds
        const __half* src = in + (size_t)r*Hd + c8;
        cp_async16(dst, src, nb);
    }
}

// warp tile: 32 rows x 32 cols; acc[mt][nt][4]
__device__ __forceinline__ void gemm_1t(uint32_t sb, int a_off, int w_h,
                                        float acc[2][4][4], int m0, int wn, int lane){
    uint32_t aaddr  = sb + 2u*((uint32_t)(a_off + (m0 + (lane&15))*LDA + (lane>>4)*8));
    uint32_t baddrh = sb + 2u*((uint32_t)(w_h + (lane&15)*LDA + wn*32 + (lane>>4)*8));
    #pragma unroll
    for (int kb = 0; kb < 8; kb++){
        uint32_t a0[4], a1[4];
        ldsm_x4(a0[0], a0[1], a0[2], a0[3], aaddr + kb*32);
        ldsm_x4(a1[0], a1[1], a1[2], a1[3], aaddr + 16*LDA*2 + kb*32);
        uint32_t bstep = (uint32_t)kb*(16*LDA*2);
        #pragma unroll
        for (int ntp = 0; ntp < 2; ntp++){
            uint32_t bh[4];
            ldsm_x4t(bh, baddrh + bstep + ntp*32);
            mma_fp16(acc[0][2*ntp],   a0, bh[0], bh[1]);
            mma_fp16(acc[1][2*ntp],   a1, bh[0], bh[1]);
            mma_fp16(acc[0][2*ntp+1], a0, bh[2], bh[3]);
            mma_fp16(acc[1][2*ntp+1], a1, bh[2], bh[3]);
        }
    }
}

__global__ void __launch_bounds__(512, 1)
k_mlp_mma(const __half* __restrict__ in, __half* __restrict__ out,
          const __half* __restrict__ wa, const __half* __restrict__ wb,
          const float* __restrict__ ba, const float* __restrict__ bb,
          int rows, int outer_gelu){
    extern __shared__ __half sm[];
    const uint32_t sb = smem_u32(sm);
    const int tid = threadIdx.x;
    const int ntiles = (rows + 127) >> 7;

    {   // weights gmem -> padded smem, ONCE per CTA
        const uint4* s0 = (const uint4*)wa; const uint4* s1 = (const uint4*)wb;
        #pragma unroll
        for (int i = tid; i < 2048; i += 512){
            int row = i >> 4, c8 = (i & 15)*8;
            int d = row*LDA + c8;
            *(uint4*)&sm[SM_WAH + d] = s0[i];
            *(uint4*)&sm[SM_WBH + d] = s1[i];
        }
    }
    int tile = blockIdx.x;
    if (tile < ntiles) load_A_async(sb, in, tile << 7, rows, tid);
    CP_COMMIT();

    const int w = tid >> 5, lane = tid & 31;
    const int wm = w & 3, wn = w >> 2;   // 4 m-groups (32 rows) x 4 n-groups (32 cols)
    const int m0 = wm*32;
    const int grp = lane >> 2, quad = lane & 3;
    const int pair_bar = 1 + wm;
    int buf = 0;

    for (; tile < ntiles; tile += MLP_GRID){
        CP_WAIT0();
        __syncthreads();
        int next = tile + MLP_GRID;
        if (next < ntiles) load_A_async(sb + (buf ? 0u : 2u*SM_A1), in, next << 7, rows, tid);
        CP_COMMIT();

        const int a_off = buf ? SM_A1 : SM_A0;
        const int base = tile << 7;
        float acc[2][4][4];

        // ---- GEMM1 ----
        #pragma unroll
        for (int mt = 0; mt < 2; mt++)
            #pragma unroll
            for (int nt = 0; nt < 4; nt++){ acc[mt][nt][0]=0.f; acc[mt][nt][1]=0.f; acc[mt][nt][2]=0.f; acc[mt][nt][3]=0.f; }
        gemm_1t(sb, a_off, SM_WAH, acc, m0, wn, lane);
        BARW(pair_bar);

        // epilogue 1: +bias, gelu, back into A(buf)
        #pragma unroll
        for (int mt = 0; mt < 2; mt++){
            int r0 = m0 + mt*16 + grp, r1 = r0 + 8;
            #pragma unroll
            for (int nt = 0; nt < 4; nt++){
                int n = wn*32 + nt*8 + quad*2;
                float b0 = ba[n], b1 = ba[n+1];
                float v00 = gelu_f(acc[mt][nt][0] + b0), v01 = gelu_f(acc[mt][nt][1] + b1);
                float v10 = gelu_f(acc[mt][nt][2] + b0), v11 = gelu_f(acc[mt][nt][3] + b1);
                *(uint32_t*)&sm[a_off + r0*LDA + n] = pack_h2(v00, v01);
                *(uint32_t*)&sm[a_off + r1*LDA + n] = pack_h2(v10, v11);
            }
        }
        BARW(pair_bar);

        // ---- GEMM2 ----
        #pragma unroll
        for (int mt = 0; mt < 2; mt++)
            #pragma unroll
            for (int nt = 0; nt < 4; nt++){ acc[mt][nt][0]=0.f; acc[mt][nt][1]=0.f; acc[mt][nt][2]=0.f; acc[mt][nt][3]=0.f; }
        gemm_1t(sb, a_off, SM_WBH, acc, m0, wn, lane);

        // epilogue 2: +bias, optional gelu, store fp16
        #pragma unroll
        for (int mt = 0; mt < 2; mt++){
            int r0 = m0 + mt*16 + grp, r1 = r0 + 8;
            bool v0 = (base + r0) < rows, v1 = (base + r1) < rows;
            #pragma unroll
            for (int nt = 0; nt < 4; nt++){
                int n = wn*32 + nt*8 + quad*2;
                float b0 = bb[n], b1 = bb[n+1];
                float o00 = acc[mt][nt][0] + b0, o01 = acc[mt][nt][1] + b1;
                float o10 = acc[mt][nt][2] + b0, o11 = acc[mt][nt][3] + b1;
                if (outer_gelu){ o00=gelu_f(o00); o01=gelu_f(o01); o10=gelu_f(o10); o11=gelu_f(o11); }
                if (v0) *(uint32_t*)&out[(size_t)(base+r0)*Hd + n] = pack_h2(o00, o01);
                if (v1) *(uint32_t*)&out[(size_t)(base+r1)*Hd + n] = pack_h2(o10, o11);
            }
        }
        buf ^= 1;
    }
}

// ---------------- zero counters ----------------
__global__ void k_zero_counts(){
    int i = blockIdx.x*256 + threadIdx.x;
    if (i < Nn){ g_deg[i]=0; g_cnt[i]=0; }
}

// ---------------- CSR build on dst ----------------
__global__ void k_hist(const int* __restrict__ dst){
    int e = blockIdx.x*256 + threadIdx.x;
    if (e < Ee) atomicAdd(&g_deg[dst[e]], 1);
}

__global__ void k_scan1(){
    __shared__ int s[1024];
    int tid = threadIdx.x;
    int i = blockIdx.x*1024 + tid;
    int v = (i<Nn) ? g_deg[i] : 0;
    s[tid] = v; __syncthreads();
    #pragma unroll
    for (int off=1; off<1024; off<<=1){
        int t = (tid>=off) ? s[tid-off] : 0;
        __syncthreads();
        s[tid] += t;
        __syncthreads();
    }
    if (i<Nn) g_offs[i] = s[tid] - v;
    if (tid==1023) g_bsum[blockIdx.x] = s[1023];
}

__global__ void k_scan2(){
    if (threadIdx.x==0){
        int acc = 0;
        for (int b=0;b<NBLK_SCAN;b++){ g_boff[b]=acc; acc+=g_bsum[b]; }
        g_boff[NBLK_SCAN]=acc;
        g_offs[Nn]=acc;
    }
}

__global__ void k_scan3(){
    int i = blockIdx.x*1024 + threadIdx.x;
    if (i<Nn) g_offs[i] += g_boff[blockIdx.x];
}

__global__ void k_fill(const int* __restrict__ dst){
    int e = blockIdx.x*256 + threadIdx.x;
    if (e < Ee){
        int d = dst[e];
        int p = atomicAdd(&g_cnt[d], 1);
        g_csr[g_offs[d]+p] = e;
    }
}

// ---------------- graph boundaries ----------------
__global__ void k_gstart(const int* __restrict__ batch){
    int g = threadIdx.x;
    if (g > Gg) return;
    int lo = 0, hi = Nn;
    while (lo < hi){
        int mid = (lo+hi) >> 1;
        if (batch[mid] < g) lo = mid+1; else hi = mid;
    }
    g_gstart[g] = lo;
}

// ---------------- aggregation: shfl index broadcast + 8-wide value batches ----------------
// 128 thr: warp = centroid, lane = 4 comps. Indices fetched 32-wide in parallel,
// values loaded 8 edges back-to-back (MLP=8), accumulation in exact k-order.
__global__ void k_agg(const __half* __restrict__ xin, const float* __restrict__ em,
                      const int* __restrict__ src, const float* __restrict__ epsp,
                      int l, __half* __restrict__ hout){
    const int n = blockIdx.x;
    const int c = threadIdx.x >> 5;      // warp = centroid
    const int i = threadIdx.x & 31;      // lane covers 4 components (uint2)
    const float ep = 1.0f + epsp[l];
    const int beg = g_offs[n], end = g_offs[n+1];
    const uint2* xc = (const uint2*)xin + (size_t)c*Nn*32;
    const uint2* ee4 = (const uint2*)g_eeh;
    const float* emc = em + (size_t)c*Ee;

    float4 a;
    {
        uint2 u = xc[(size_t)n*32 + i];
        __half2 h0, h1; memcpy(&h0, &u.x, 4); memcpy(&h1, &u.y, 4);
        float2 v0 = __half22float2(h0), v1 = __half22float2(h1);
        a.x = ep*v0.x; a.y = ep*v0.y; a.z = ep*v1.x; a.w = ep*v1.y;
    }
    for (int kb = beg; kb < end; kb += 32){
        int cn = end - kb; if (cn > 32) cn = 32;
        // parallel index fetch: lane j holds edge kb+j
        int eL = 0, sL = 0;
        if (i < cn){ eL = g_csr[kb + i]; sL = src[eL]; }
        #pragma unroll 1
        for (int j = 0; j < cn; j += 8){
            int bn = cn - j; if (bn > 8) bn = 8;
            uint2 ev[8], xv[8]; float mm[8];
            #pragma unroll
            for (int u = 0; u < 8; u++){
                int e = __shfl_sync(0xFFFFFFFFu, eL, j + u);
                int s = __shfl_sync(0xFFFFFFFFu, sL, j + u);
                if (u < bn){
                    ev[u] = ee4[(size_t)e*32 + i];
                    xv[u] = xc[(size_t)s*32 + i];
                    mm[u] = emc[e];
                }
            }
            #pragma unroll
            for (int u = 0; u < 8; u++){
                if (u < bn){
                    __half2 eh0, eh1, xh0, xh1;
                    memcpy(&eh0, &ev[u].x, 4); memcpy(&eh1, &ev[u].y, 4);
                    memcpy(&xh0, &xv[u].x, 4); memcpy(&xh1, &xv[u].y, 4);
                    float2 e0 = __half22float2(eh0), e1 = __half22float2(eh1);
                    float2 x0 = __half22float2(xh0), x1 = __half22float2(xh1);
                    float m = mm[u];
                    a.x += gelu_f(x0.x + e0.x) * m;
                    a.y += gelu_f(x0.y + e0.y) * m;
                    a.z += gelu_f(x1.x + e1.x) * m;
                    a.w += gelu_f(x1.y + e1.y) * m;
                }
            }
        }
    }
    uint2 o; o.x = pack_h2(a.x, a.y); o.y = pack_h2(a.z, a.w);
    ((uint2*)hout)[(size_t)c*Nn*32 + (size_t)n*32 + i] = o;
}

// ---------------- masked mean pool ----------------
__global__ void k_pool(const __half* __restrict__ y, const float* __restrict__ nm,
                       float* __restrict__ out){
    __shared__ float snum[512];
    __shared__ float sden[4];
    int f = threadIdx.x & 127;
    int slice = threadIdx.x >> 7;
    int g = blockIdx.x, c = blockIdx.y;
    int beg = g_gstart[g], end = g_gstart[g+1];
    float num = 0.f, den = 0.f;
    for (int n=beg+slice; n<end; n+=4){
        float m = nm[c*Nn+n];
        num += __half2float(y[(size_t)(c*Nn+n)*Hd+f])*m;
        den += m;
    }
    snum[threadIdx.x] = num;
    if (f==0) sden[slice] = den;
    __syncthreads();
    if (slice==0){
        float tot = snum[f] + snum[128+f] + snum[256+f] + snum[384+f];
        float d = sden[0]+sden[1]+sden[2]+sden[3] + 1e-7f;
        out[(g*Cc+c)*Hd+f] = tot / d;
    }
}

// ---------------- launch ----------------
extern "C" void kernel_launch(void* const* d_in, const int* in_sizes, int n_in,
                              void* d_out, int out_size){
    const float* x    = (const float*)d_in[0];
    const int*  batch = (const int*)d_in[1];
    const int*  eidx  = (const int*)d_in[2];
    const float* ea   = (const float*)d_in[3];
    const float* nm   = (const float*)d_in[4];
    const float* em   = (const float*)d_in[5];
    const float* Wbe  = (const float*)d_in[6];
    const float* bbe  = (const float*)d_in[7];
    const float* eps  = (const float*)d_in[8];
    const float* W1   = (const float*)d_in[9];
    const float* b1   = (const float*)d_in[10];
    const float* W2   = (const float*)d_in[11];
    const float* b2   = (const float*)d_in[12];
    const float* Wm1  = (const float*)d_in[13];
    const float* bm1  = (const float*)d_in[14];
    const float* Wm2  = (const float*)d_in[15];
    const float* bm2  = (const float*)d_in[16];
    float* out = (float*)d_out;

    const int* src = eidx;
    const int* dst = eidx + Ee;

    __half *xh, *bufA, *bufB, *wsp;
    cudaGetSymbolAddress((void**)&xh,   g_xh);
    cudaGetSymbolAddress((void**)&bufA, g_bufA);
    cudaGetSymbolAddress((void**)&bufB, g_bufB);
    cudaGetSymbolAddress((void**)&wsp,  g_wsp);
    cudaFuncSetAttribute(k_mlp_mma, cudaFuncAttributeMaxDynamicSharedMemorySize, SMEM_MMA);

    // prep
    k_prepw_all<<<dim3(64, 6), 256>>>(W1, W2, Wm1, Wm2, wsp);
    k_x2h<<<(NROWS*Hd/4 + 255)/256, 256>>>(x, xh);
    k_zero_counts<<<(Nn+255)/256, 256>>>();
    k_bond_mma<<<(Ee+255)/256, 512>>>(ea, Wbe, bbe);
    k_hist<<<(Ee+255)/256, 256>>>(dst);
    k_scan1<<<NBLK_SCAN, 1024>>>();
    k_scan2<<<1, 32>>>();
    k_scan3<<<NBLK_SCAN, 1024>>>();
    k_fill<<<(Ee+255)/256, 256>>>(dst);
    k_gstart<<<1, 128>>>(batch);

    // layer 0
    k_agg<<<Nn, 128>>>(xh, em, src, eps, 0, bufA);
    k_mlp_mma<<<MLP_GRID, 512, SMEM_MMA>>>(bufA, bufB,
        wsp + 0*16384, wsp + 1*16384, b1, b2, NROWS, 1);
    // layer 1
    k_agg<<<Nn, 128>>>(bufB, em, src, eps, 1, bufA);
    k_mlp_mma<<<MLP_GRID, 512, SMEM_MMA>>>(bufA, bufB,
        wsp + 2*16384, wsp + 3*16384, b1 + Hd, b2 + Hd, NROWS, 1);
    // final MLP (no outer gelu)
    k_mlp_mma<<<MLP_GRID, 512, SMEM_MMA>>>(bufB, bufA,
        wsp + 4*16384, wsp + 5*16384, bm1, bm2, NROWS, 0);
    // pool
    k_pool<<<dim3(Gg, Cc), 512>>>(bufA, nm, out);
}

// round 17
// speedup vs baseline: 1.0315x; 1.0315x over previous
#include <cuda_runtime.h>
#include <cuda_fp16.h>
#include <cstdint>
#include <cstring>
#include <math.h>

#define Nn 50000
#define Ee 200000
#define Hd 128
#define Cc 4
#define Gg 64
#define EDd 16
#define NROWS (Cc*Nn)   // 200000
#define NBLK_SCAN ((Nn + 1023)/1024)   // 49
#define MLP_GRID 304

// ---------------- scratch (device globals; no allocation allowed) ----------------
__device__ __align__(128) __half g_eeh[Ee*Hd];
__device__ __align__(128) __half g_xh[NROWS*Hd];
__device__ __align__(128) __half g_bufA[NROWS*Hd];
__device__ __align__(128) __half g_bufB[NROWS*Hd];
__device__ int g_deg[Nn];
__device__ int g_offs[Nn+1];
__device__ int g_cnt[Nn];
__device__ int g_csr[Ee];
__device__ int g_gstart[Gg+1];
__device__ int g_bsum[NBLK_SCAN];
__device__ int g_boff[NBLK_SCAN+1];
// fp16 weights: 6 matrices x 16384, row-major [k][n]
__device__ __align__(128) __half g_wsp[6*16384];

__device__ __forceinline__ float gelu_f(float v){
    return 0.5f*v*(1.0f+erff(v*0.7071067811865475f));
}

__device__ __forceinline__ uint32_t smem_u32(const void* p){
    uint32_t a;
    asm("{ .reg .u64 t; cvta.to.shared.u64 t, %1; cvt.u32.u64 %0, t; }" : "=r"(a) : "l"(p));
    return a;
}
__device__ __forceinline__ void ldsm_x4(uint32_t& r0, uint32_t& r1, uint32_t& r2, uint32_t& r3, uint32_t addr){
    asm volatile("ldmatrix.sync.aligned.m8n8.x4.shared.b16 {%0,%1,%2,%3}, [%4];"
        : "=r"(r0), "=r"(r1), "=r"(r2), "=r"(r3) : "r"(addr));
}
__device__ __forceinline__ void ldsm_x4t(uint32_t* r, uint32_t addr){
    asm volatile("ldmatrix.sync.aligned.m8n8.x4.trans.shared.b16 {%0,%1,%2,%3}, [%4];"
        : "=r"(r[0]), "=r"(r[1]), "=r"(r[2]), "=r"(r[3]) : "r"(addr));
}
__device__ __forceinline__ void mma_fp16(float* c, const uint32_t* a, uint32_t b0, uint32_t b1){
    asm volatile("mma.sync.aligned.m16n8k16.row.col.f32.f16.f16.f32 "
        "{%0,%1,%2,%3},{%4,%5,%6,%7},{%8,%9},{%0,%1,%2,%3};"
        : "+f"(c[0]), "+f"(c[1]), "+f"(c[2]), "+f"(c[3])
        : "r"(a[0]), "r"(a[1]), "r"(a[2]), "r"(a[3]), "r"(b0), "r"(b1));
}
__device__ __forceinline__ uint32_t pack_h2(float a, float b){
    __half2 t = __floats2half2_rn(a, b);
    uint32_t u; memcpy(&u, &t, 4); return u;
}
#define BARW(id) asm volatile("bar.sync %0, 128;" :: "r"(id) : "memory")

// ---------------- weight prep: fp32 -> fp16 (all 6 mats) ----------------
__global__ void k_prepw_all(const float* __restrict__ W1, const float* __restrict__ W2,
                            const float* __restrict__ Wm1, const float* __restrict__ Wm2,
                            __half* __restrict__ outw){
    int mat = blockIdx.y;
    const float* src;
    switch (mat){
        case 0: src = W1;          break;
        case 1: src = W2;          break;
        case 2: src = W1 + 16384;  break;
        case 3: src = W2 + 16384;  break;
        case 4: src = Wm1;         break;
        default: src = Wm2;        break;
    }
    int idx = blockIdx.x*256 + threadIdx.x;
    if (idx >= 16384) return;
    outw[mat*16384 + idx] = __float2half_rn(src[idx]);
}

// ---------------- x fp32 -> fp16 ----------------
__global__ void k_x2h(const float* __restrict__ x, __half* __restrict__ xh){
    int i = blockIdx.x*256 + threadIdx.x;
    if (i < NROWS*Hd/4){
        float4 v = ((const float4*)x)[i];
        uint2 o; o.x = pack_h2(v.x, v.y); o.y = pack_h2(v.z, v.w);
        ((uint2*)xh)[i] = o;
    }
}

// ---------------- bond encoder via mma (single fp16 W term) ----------------
#define LDB_A 24
__global__ void __launch_bounds__(512, 2)
k_bond_mma(const float* __restrict__ ea, const float* __restrict__ Wbe,
           const float* __restrict__ bbe){
    __shared__ __half sA[256*LDB_A];
    __shared__ __half sWh[16*136];
    const int tid = threadIdx.x;
    const int base = blockIdx.x*256;

    #pragma unroll
    for (int i = tid; i < 2048; i += 512){
        int k = i >> 7, n = i & 127;
        sWh[k*136 + n] = __float2half_rn(Wbe[i]);
    }
    #pragma unroll
    for (int i = tid; i < 1024; i += 512){
        int row = i >> 2, c4 = (i & 3)*4;
        float4 v = make_float4(0.f,0.f,0.f,0.f);
        if (base + row < Ee) v = *(const float4*)&ea[(size_t)(base+row)*EDd + c4];
        uint2 o; o.x = pack_h2(v.x, v.y); o.y = pack_h2(v.z, v.w);
        *(uint2*)&sA[row*LDB_A + c4] = o;
    }
    __syncthreads();

    const uint32_t sbA = smem_u32(sA), sbWh = smem_u32(sWh);
    const int w = tid >> 5, lane = tid & 31;
    const int wm = w & 7, wn = w >> 3;
    const int m0 = wm*32;
    const int grp = lane >> 2, quad = lane & 3;

    uint32_t a0[4], a1[4];
    {
        uint32_t aaddr = sbA + 2u*((uint32_t)((m0 + (lane&15))*LDB_A + (lane>>4)*8));
        ldsm_x4(a0[0], a0[1], a0[2], a0[3], aaddr);
        ldsm_x4(a1[0], a1[1], a1[2], a1[3], aaddr + 16*LDB_A*2);
    }
    float acc[2][8][4];
    #pragma unroll
    for (int mt = 0; mt < 2; mt++)
        #pragma unroll
        for (int nt = 0; nt < 8; nt++){ acc[mt][nt][0]=0.f; acc[mt][nt][1]=0.f; acc[mt][nt][2]=0.f; acc[mt][nt][3]=0.f; }

    {
        uint32_t bh_base = sbWh + 2u*((uint32_t)((lane&15)*136 + wn*64 + (lane>>4)*8));
        #pragma unroll
        for (int ntp = 0; ntp < 4; ntp++){
            uint32_t bh[4];
            ldsm_x4t(bh, bh_base + ntp*32);
            mma_fp16(acc[0][2*ntp],   a0, bh[0], bh[1]);
            mma_fp16(acc[1][2*ntp],   a1, bh[0], bh[1]);
            mma_fp16(acc[0][2*ntp+1], a0, bh[2], bh[3]);
            mma_fp16(acc[1][2*ntp+1], a1, bh[2], bh[3]);
        }
    }
    #pragma unroll
    for (int mt = 0; mt < 2; mt++){
        int r0 = m0 + mt*16 + grp, r1 = r0 + 8;
        bool v0 = (base + r0) < Ee, v1 = (base + r1) < Ee;
        #pragma unroll
        for (int nt = 0; nt < 8; nt++){
            int n = wn*64 + nt*8 + quad*2;
            float b0 = bbe[n], b1 = bbe[n+1];
            if (v0) *(uint32_t*)&g_eeh[(size_t)(base+r0)*Hd + n] = pack_h2(acc[mt][nt][0]+b0, acc[mt][nt][1]+b1);
            if (v1) *(uint32_t*)&g_eeh[(size_t)(base+r1)*Hd + n] = pack_h2(acc[mt][nt][2]+b0, acc[mt][nt][3]+b1);
        }
    }
}

// ---------------- persistent mma MLP: single A buffer, 2 CTAs/SM ----------------
#define LDA 136
#define SM_A   0
#define SM_WAH (128*LDA)
#define SM_WBH (128*LDA + 128*LDA)
#define SMEM_MMA ((3*128*LDA)*2)   // 104448 bytes -> 2 CTAs/SM

__device__ __forceinline__ void cp_async16(uint32_t dst, const void* src, int nbytes){
    asm volatile("cp.async.ca.shared.global [%0], [%1], 16, %2;"
        :: "r"(dst), "l"(src), "r"(nbytes));
}
#define CP_COMMIT() asm volatile("cp.async.commit_group;" ::: "memory")
#define CP_WAIT0()  asm volatile("cp.async.wait_group 0;" ::: "memory")

__device__ __forceinline__ void load_A_async(uint32_t sbuf, const __half* __restrict__ in,
                                             int base, int rows, int tid){
    #pragma unroll
    for (int i = tid; i < 2048; i += 512){
        int row = i >> 4, c8 = (i & 15)*8;
        uint32_t dst = sbuf + 2u*((uint32_t)(row*LDA + c8));
        int r = base + row;
        int nb = (r < rows) ? 16 : 0;
        if (r >= rows) r = rows - 1;              // clamp: address always in-bounds
        const __half* src = in + (size_t)r*Hd + c8;
        cp_async16(dst, src, nb);
    }
}

// warp tile: 32 rows x 32 cols; acc[mt][nt][4]
__device__ __forceinline__ void gemm_1t(uint32_t sb, int w_h,
                                        float acc[2][4][4], int m0, int wn, int lane){
    uint32_t aaddr  = sb + 2u*((uint32_t)(SM_A + (m0 + (lane&15))*LDA + (lane>>4)*8));
    uint32_t baddrh = sb + 2u*((uint32_t)(w_h + (lane&15)*LDA + wn*32 + (lane>>4)*8));
    #pragma unroll
    for (int kb = 0; kb < 8; kb++){
        uint32_t a0[4], a1[4];
        ldsm_x4(a0[0], a0[1], a0[2], a0[3], aaddr + kb*32);
        ldsm_x4(a1[0], a1[1], a1[2], a1[3], aaddr + 16*LDA*2 + kb*32);
        uint32_t bstep = (uint32_t)kb*(16*LDA*2);
        #pragma unroll
        for (int ntp = 0; ntp < 2; ntp++){
            uint32_t bh[4];
            ldsm_x4t(bh, baddrh + bstep + ntp*32);
            mma_fp16(acc[0][2*ntp],   a0, bh[0], bh[1]);
            mma_fp16(acc[1][2*ntp],   a1, bh[0], bh[1]);
            mma_fp16(acc[0][2*ntp+1], a0, bh[2], bh[3]);
            mma_fp16(acc[1][2*ntp+1], a1, bh[2], bh[3]);
        }
    }
}

__global__ void __launch_bounds__(512, 2)
k_mlp_mma(const __half* __restrict__ in, __half* __restrict__ out,
          const __half* __restrict__ wa, const __half* __restrict__ wb,
          const float* __restrict__ ba, const float* __restrict__ bb,
          int rows, int outer_gelu){
    extern __shared__ __half sm[];
    const uint32_t sb = smem_u32(sm);
    const int tid = threadIdx.x;
    const int ntiles = (rows + 127) >> 7;

    {   // weights gmem -> padded smem, ONCE per CTA
        const uint4* s0 = (const uint4*)wa; const uint4* s1 = (const uint4*)wb;
        #pragma unroll
        for (int i = tid; i < 2048; i += 512){
            int row = i >> 4, c8 = (i & 15)*8;
            int d = row*LDA + c8;
            *(uint4*)&sm[SM_WAH + d] = s0[i];
            *(uint4*)&sm[SM_WBH + d] = s1[i];
        }
    }

    const int w = tid >> 5, lane = tid & 31;
    const int wm = w & 3, wn = w >> 2;   // 4 m-groups (32 rows) x 4 n-groups (32 cols)
    const int m0 = wm*32;
    const int grp = lane >> 2, quad = lane & 3;
    const int pair_bar = 1 + wm;

    for (int tile = blockIdx.x; tile < ntiles; tile += MLP_GRID){
        load_A_async(sb, in, tile << 7, rows, tid);
        CP_COMMIT();
        CP_WAIT0();
        __syncthreads();     // A ready for all warps

        const int base = tile << 7;
        float acc[2][4][4];

        // ---- GEMM1 ----
        #pragma unroll
        for (int mt = 0; mt < 2; mt++)
            #pragma unroll
            for (int nt = 0; nt < 4; nt++){ acc[mt][nt][0]=0.f; acc[mt][nt][1]=0.f; acc[mt][nt][2]=0.f; acc[mt][nt][3]=0.f; }
        gemm_1t(sb, SM_WAH, acc, m0, wn, lane);
        BARW(pair_bar);      // row-group done reading A before overwrite

        // epilogue 1: +bias, gelu, back into A
        #pragma unroll
        for (int mt = 0; mt < 2; mt++){
            int r0 = m0 + mt*16 + grp, r1 = r0 + 8;
            #pragma unroll
            for (int nt = 0; nt < 4; nt++){
                int n = wn*32 + nt*8 + quad*2;
                float b0 = ba[n], b1 = ba[n+1];
                float v00 = gelu_f(acc[mt][nt][0] + b0), v01 = gelu_f(acc[mt][nt][1] + b1);
                float v10 = gelu_f(acc[mt][nt][2] + b0), v11 = gelu_f(acc[mt][nt][3] + b1);
                *(uint32_t*)&sm[SM_A + r0*LDA + n] = pack_h2(v00, v01);
                *(uint32_t*)&sm[SM_A + r1*LDA + n] = pack_h2(v10, v11);
            }
        }
        BARW(pair_bar);      // row-group writes visible before GEMM2 reads

        // ---- GEMM2 ----
        #pragma unroll
        for (int mt = 0; mt < 2; mt++)
            #pragma unroll
            for (int nt = 0; nt < 4; nt++){ acc[mt][nt][0]=0.f; acc[mt][nt][1]=0.f; acc[mt][nt][2]=0.f; acc[mt][nt][3]=0.f; }
        gemm_1t(sb, SM_WBH, acc, m0, wn, lane);

        // epilogue 2: +bias, optional gelu, store fp16
        #pragma unroll
        for (int mt = 0; mt < 2; mt++){
            int r0 = m0 + mt*16 + grp, r1 = r0 + 8;
            bool v0 = (base + r0) < rows, v1 = (base + r1) < rows;
            #pragma unroll
            for (int nt = 0; nt < 4; nt++){
                int n = wn*32 + nt*8 + quad*2;
                float b0 = bb[n], b1 = bb[n+1];
                float o00 = acc[mt][nt][0] + b0, o01 = acc[mt][nt][1] + b1;
                float o10 = acc[mt][nt][2] + b0, o11 = acc[mt][nt][3] + b1;
                if (outer_gelu){ o00=gelu_f(o00); o01=gelu_f(o01); o10=gelu_f(o10); o11=gelu_f(o11); }
                if (v0) *(uint32_t*)&out[(size_t)(base+r0)*Hd + n] = pack_h2(o00, o01);
                if (v1) *(uint32_t*)&out[(size_t)(base+r1)*Hd + n] = pack_h2(o10, o11);
            }
        }
        __syncthreads();     // all reads of A done before next tile's load overwrites
    }
}

// ---------------- zero counters ----------------
__global__ void k_zero_counts(){
    int i = blockIdx.x*256 + threadIdx.x;
    if (i < Nn){ g_deg[i]=0; g_cnt[i]=0; }
}

// ---------------- CSR build on dst ----------------
__global__ void k_hist(const int* __restrict__ dst){
    int e = blockIdx.x*256 + threadIdx.x;
    if (e < Ee) atomicAdd(&g_deg[dst[e]], 1);
}

__global__ void k_scan1(){
    __shared__ int s[1024];
    int tid = threadIdx.x;
    int i = blockIdx.x*1024 + tid;
    int v = (i<Nn) ? g_deg[i] : 0;
    s[tid] = v; __syncthreads();
    #pragma unroll
    for (int off=1; off<1024; off<<=1){
        int t = (tid>=off) ? s[tid-off] : 0;
        __syncthreads();
        s[tid] += t;
        __syncthreads();
    }
    if (i<Nn) g_offs[i] = s[tid] - v;
    if (tid==1023) g_bsum[blockIdx.x] = s[1023];
}

__global__ void k_scan2(){
    if (threadIdx.x==0){
        int acc = 0;
        for (int b=0;b<NBLK_SCAN;b++){ g_boff[b]=acc; acc+=g_bsum[b]; }
        g_boff[NBLK_SCAN]=acc;
        g_offs[Nn]=acc;
    }
}

__global__ void k_scan3(){
    int i = blockIdx.x*1024 + threadIdx.x;
    if (i<Nn) g_offs[i] += g_boff[blockIdx.x];
}

__global__ void k_fill(const int* __restrict__ dst){
    int e = blockIdx.x*256 + threadIdx.x;
    if (e < Ee){
        int d = dst[e];
        int p = atomicAdd(&g_cnt[d], 1);
        g_csr[g_offs[d]+p] = e;
    }
}

// ---------------- graph boundaries ----------------
__global__ void k_gstart(const int* __restrict__ batch){
    int g = threadIdx.x;
    if (g > Gg) return;
    int lo = 0, hi = Nn;
    while (lo < hi){
        int mid = (lo+hi) >> 1;
        if (batch[mid] < g) lo = mid+1; else hi = mid;
    }
    g_gstart[g] = lo;
}

// ---------------- aggregation: 128 thr (warp = centroid, lane = 4 comps), value-pipelined ----------------
__global__ void k_agg(const __half* __restrict__ xin, const float* __restrict__ em,
                      const int* __restrict__ src, const float* __restrict__ epsp,
                      int l, __half* __restrict__ hout){
    const int n = blockIdx.x;
    const int c = threadIdx.x >> 5;      // warp = centroid
    const int i = threadIdx.x & 31;      // lane covers 4 components (uint2 = 2 half2)
    const float ep = 1.0f + epsp[l];
    const int beg = g_offs[n], end = g_offs[n+1];
    const uint2* xc = (const uint2*)xin + (size_t)c*Nn*32;
    const uint2* ee4 = (const uint2*)g_eeh;

    float4 a;
    {
        uint2 u = xc[(size_t)n*32 + i];
        __half2 h0, h1; memcpy(&h0, &u.x, 4); memcpy(&h1, &u.y, 4);
        float2 v0 = __half22float2(h0), v1 = __half22float2(h1);
        a.x = ep*v0.x; a.y = ep*v0.y; a.z = ep*v1.x; a.w = ep*v1.y;
    }
    if (beg < end){
        int e = g_csr[beg];
        int s = src[e];
        uint2 ev = ee4[(size_t)e*32 + i];
        uint2 xv = xc[(size_t)s*32 + i];
        float m = em[(size_t)c*Ee + e];
        for (int k = beg; k < end; k++){
            uint2 ev_n = ev, xv_n = xv; float m_n = m;
            if (k + 1 < end){
                int e2 = g_csr[k+1];
                int s2 = src[e2];
                ev_n = ee4[(size_t)e2*32 + i];
                xv_n = xc[(size_t)s2*32 + i];
                m_n = em[(size_t)c*Ee + e2];
            }
            __half2 eh0, eh1, xh0, xh1;
            memcpy(&eh0, &ev.x, 4); memcpy(&eh1, &ev.y, 4);
            memcpy(&xh0, &xv.x, 4); memcpy(&xh1, &xv.y, 4);
            float2 e0 = __half22float2(eh0), e1 = __half22float2(eh1);
            float2 x0 = __half22float2(xh0), x1 = __half22float2(xh1);
            a.x += gelu_f(x0.x + e0.x) * m;
            a.y += gelu_f(x0.y + e0.y) * m;
            a.z += gelu_f(x1.x + e1.x) * m;
            a.w += gelu_f(x1.y + e1.y) * m;
            ev = ev_n; xv = xv_n; m = m_n;
        }
    }
    uint2 o; o.x = pack_h2(a.x, a.y); o.y = pack_h2(a.z, a.w);
    ((uint2*)hout)[(size_t)c*Nn*32 + (size_t)n*32 + i] = o;
}

// ---------------- masked mean pool ----------------
__global__ void k_pool(const __half* __restrict__ y, const float* __restrict__ nm,
                       float* __restrict__ out){
    __shared__ float snum[512];
    __shared__ float sden[4];
    int f = threadIdx.x & 127;
    int slice = threadIdx.x >> 7;
    int g = blockIdx.x, c = blockIdx.y;
    int beg = g_gstart[g], end = g_gstart[g+1];
    float num = 0.f, den = 0.f;
    for (int n=beg+slice; n<end; n+=4){
        float m = nm[c*Nn+n];
        num += __half2float(y[(size_t)(c*Nn+n)*Hd+f])*m;
        den += m;
    }
    snum[threadIdx.x] = num;
    if (f==0) sden[slice] = den;
    __syncthreads();
    if (slice==0){
        float tot = snum[f] + snum[128+f] + snum[256+f] + snum[384+f];
        float d = sden[0]+sden[1]+sden[2]+sden[3] + 1e-7f;
        out[(g*Cc+c)*Hd+f] = tot / d;
    }
}

// ---------------- launch ----------------
extern "C" void kernel_launch(void* const* d_in, const int* in_sizes, int n_in,
                              void* d_out, int out_size){
    const float* x    = (const float*)d_in[0];
    const int*  batch = (const int*)d_in[1];
    const int*  eidx  = (const int*)d_in[2];
    const float* ea   = (const float*)d_in[3];
    const float* nm   = (const float*)d_in[4];
    const float* em   = (const float*)d_in[5];
    const float* Wbe  = (const float*)d_in[6];
    const float* bbe  = (const float*)d_in[7];
    const float* eps  = (const float*)d_in[8];
    const float* W1   = (const float*)d_in[9];
    const float* b1   = (const float*)d_in[10];
    const float* W2   = (const float*)d_in[11];
    const float* b2   = (const float*)d_in[12];
    const float* Wm1  = (const float*)d_in[13];
    const float* bm1  = (const float*)d_in[14];
    const float* Wm2  = (const float*)d_in[15];
    const float* bm2  = (const float*)d_in[16];
    float* out = (float*)d_out;

    const int* src = eidx;
    const int* dst = eidx + Ee;

    __half *xh, *bufA, *bufB, *wsp;
    cudaGetSymbolAddress((void**)&xh,   g_xh);
    cudaGetSymbolAddress((void**)&bufA, g_bufA);
    cudaGetSymbolAddress((void**)&bufB, g_bufB);
    cudaGetSymbolAddress((void**)&wsp,  g_wsp);
    cudaFuncSetAttribute(k_mlp_mma, cudaFuncAttributeMaxDynamicSharedMemorySize, SMEM_MMA);

    // prep
    k_prepw_all<<<dim3(64, 6), 256>>>(W1, W2, Wm1, Wm2, wsp);
    k_x2h<<<(NROWS*Hd/4 + 255)/256, 256>>>(x, xh);
    k_zero_counts<<<(Nn+255)/256, 256>>>();
    k_bond_mma<<<(Ee+255)/256, 512>>>(ea, Wbe, bbe);
    k_hist<<<(Ee+255)/256, 256>>>(dst);
    k_scan1<<<NBLK_SCAN, 1024>>>();
    k_scan2<<<1, 32>>>();
    k_scan3<<<NBLK_SCAN, 1024>>>();
    k_fill<<<(Ee+255)/256, 256>>>(dst);
    k_gstart<<<1, 128>>>(batch);

    // layer 0
    k_agg<<<Nn, 128>>>(xh, em, src, eps, 0, bufA);
    k_mlp_mma<<<MLP_GRID, 512, SMEM_MMA>>>(bufA, bufB,
        wsp + 0*16384, wsp + 1*16384, b1, b2, NROWS, 1);
    // layer 1
    k_agg<<<Nn, 128>>>(bufB, em, src, eps, 1, bufA);
    k_mlp_mma<<<MLP_GRID, 512, SMEM_MMA>>>(bufA, bufB,
        wsp + 2*16384, wsp + 3*16384, b1 + Hd, b2 + Hd, NROWS, 1);
    // final MLP (no outer gelu)
    k_mlp_mma<<<MLP_GRID, 512, SMEM_MMA>>>(bufB, bufA,
        wsp + 4*16384, wsp + 5*16384, bm1, bm2, NROWS, 0);
    // pool
    k_pool<<<dim3(Gg, Cc), 512>>>(bufA, nm, out);
}